// round 7
// baseline (speedup 1.0000x reference)
#include <cuda_runtime.h>
#include <cstdint>
#include <cstddef>

// Flash attention, warp-mma mixed precision, pipelined, m32-per-warp,
// chunk-interleaved: per 8-col chunk, MMA1 -> softmax -> MMA2, unrolled x4
// so tensor/MUFU/LSU overlap within a warp (we are issue-bound at 8 warps/SM).
//   QK^T: bf16 3-term split (m16n8k16), two m16 row-groups per warp
//   PV:   tf32 m16n8k8 on raw f32 V (HW truncation) + bias compensation

#define N_DIM 2
#define L_DIM 2048
#define S_DIM 2048
#define H_DIM 16
#define BR 128
#define BC 32
#define NTILES (S_DIM / BC)
#define TEMP 0.125f

// smem word offsets
#define KS2 36
#define VSTRIDE 72
#define PSTRIDE 40
#define QSTRIDE 68
#define KBUF 2304
#define OFF_K 0
#define OFF_V 4608
#define VBUF 2304
#define OFF_P 9216
#define SMEM_WORDS 14336
#define SMEM_BYTES (SMEM_WORDS * 4)

__device__ __forceinline__ uint32_t pack_bf16(float lo, float hi) {
    uint32_t r; asm("cvt.rn.bf16x2.f32 %0, %1, %2;" : "=r"(r) : "f"(hi), "f"(lo)); return r;
}
__device__ __forceinline__ float bf16lo_f(uint32_t u) { return __uint_as_float(u << 16); }
__device__ __forceinline__ float bf16hi_f(uint32_t u) { return __uint_as_float(u & 0xFFFF0000u); }
__device__ __forceinline__ uint32_t rna_tf32(float x) {
    uint32_t r; asm("cvt.rna.tf32.f32 %0, %1;" : "=r"(r) : "f"(x)); return r;
}

__device__ __forceinline__ void mma_bf16(float* d, const uint32_t* a, uint32_t b0, uint32_t b1) {
    asm volatile(
        "mma.sync.aligned.m16n8k16.row.col.f32.bf16.bf16.f32 "
        "{%0,%1,%2,%3}, {%4,%5,%6,%7}, {%8,%9}, {%0,%1,%2,%3};"
        : "+f"(d[0]), "+f"(d[1]), "+f"(d[2]), "+f"(d[3])
        : "r"(a[0]), "r"(a[1]), "r"(a[2]), "r"(a[3]), "r"(b0), "r"(b1));
}
__device__ __forceinline__ void mma_tf32(float* d, const uint32_t* a, uint32_t b0, uint32_t b1) {
    asm volatile(
        "mma.sync.aligned.m16n8k8.row.col.f32.tf32.tf32.f32 "
        "{%0,%1,%2,%3}, {%4,%5,%6,%7}, {%8,%9}, {%0,%1,%2,%3};"
        : "+f"(d[0]), "+f"(d[1]), "+f"(d[2]), "+f"(d[3])
        : "r"(a[0]), "r"(a[1]), "r"(a[2]), "r"(a[3]), "r"(b0), "r"(b1));
}

#define CP_ASYNC16(dst, src) \
    asm volatile("cp.async.cg.shared.global [%0], [%1], 16;" :: "r"(dst), "l"(src))
#define CP_COMMIT() asm volatile("cp.async.commit_group;" ::: "memory")
#define CP_WAIT0()  asm volatile("cp.async.wait_group 0;" ::: "memory")

__global__ __launch_bounds__(128, 2) void attn_mma5_kernel(
    const float* __restrict__ Q,
    const float* __restrict__ K,
    const float* __restrict__ V,
    const float* __restrict__ M,
    float* __restrict__ O)
{
    extern __shared__ float sm[];
    uint32_t* smu = (uint32_t*)sm;

    const int tid  = threadIdx.x;
    const int w    = tid >> 5;
    const int lane = tid & 31;
    const int g    = lane >> 2;
    const int tg   = lane & 3;
    const int pxor = (g & 4);

    const int qt = blockIdx.x % (L_DIM / BR);
    const int nh = blockIdx.x / (L_DIM / BR);
    const int h  = nh % H_DIM;
    const int n  = nh / H_DIM;
    const int qbase = qt * BR;

    const float* Qg = Q + (((size_t)n * L_DIM + qbase) * H_DIM + h) * 64;
    const float* Kg = K + ((size_t)n * S_DIM * H_DIM + h) * 64;
    const float* Vg = V + ((size_t)n * S_DIM * H_DIM + h) * 64;

    const int srow[4] = { tid >> 4, (128 + tid) >> 4, (256 + tid) >> 4, (384 + tid) >> 4 };
    const int sc4 = tid & 15;

    // ---- Prologue: Q (128x64) -> smem scratch -> bf16 hi/mid A frags ----
    #pragma unroll
    for (int i = 0; i < 16; i++) {
        int idx = i * 128 + tid;
        int row = idx >> 4, c4 = idx & 15;
        float4 v = *(const float4*)(Qg + (size_t)row * (H_DIM * 64) + c4 * 4);
        *(float4*)(sm + row * QSTRIDE + c4 * 4) = v;
    }
    __syncthreads();

    uint32_t qh0[16], qm0[16], qh1[16], qm1[16];
    #pragma unroll
    for (int rg = 0; rg < 2; rg++) {
        uint32_t* qh = rg ? qh1 : qh0;
        uint32_t* qm = rg ? qm1 : qm0;
        const int r0 = w * 32 + rg * 16 + g;
        #pragma unroll
        for (int c = 0; c < 4; c++) {
            #pragma unroll
            for (int j = 0; j < 4; j++) {
                int row = r0 + ((j & 1) ? 8 : 0);
                int col = c * 16 + 2 * tg + ((j & 2) ? 8 : 0);
                float2 v = *(const float2*)(sm + row * QSTRIDE + col);
                float x0 = v.x * TEMP, x1 = v.y * TEMP;
                uint32_t hp = pack_bf16(x0, x1);
                qh[c * 4 + j] = hp;
                qm[c * 4 + j] = pack_bf16(x0 - bf16lo_f(hp), x1 - bf16hi_f(hp));
            }
        }
    }
    __syncthreads();

    float oacc0[32], oacc1[32];
    #pragma unroll
    for (int i = 0; i < 32; i++) { oacc0[i] = 0.0f; oacc1[i] = 0.0f; }
    float rs[4] = {0.0f, 0.0f, 0.0f, 0.0f};

    const uint32_t* kbh0 = smu + OFF_K + g * KS2 + tg;
    const uint32_t* vbp0 = smu + OFF_V + tg * VSTRIDE + g;
    uint32_t* prow00 = smu + OFF_P + (w * 32 + g) * PSTRIDE;
    uint32_t* prow01 = prow00 + 8 * PSTRIDE;
    uint32_t* prow10 = prow00 + 16 * PSTRIDE;
    uint32_t* prow11 = prow00 + 24 * PSTRIDE;

    const float* Mr0 = M + (size_t)(qbase + w * 32 + g) * S_DIM + tg * 2;
    const float* Mr1 = Mr0 + (size_t)8 * S_DIM;
    const float* Mr2 = Mr0 + (size_t)16 * S_DIM;
    const float* Mr3 = Mr0 + (size_t)24 * S_DIM;

    const uint32_t vdst0 = (uint32_t)__cvta_generic_to_shared(smu + OFF_V);

    #pragma unroll
    for (int i = 0; i < 4; i++) {
        uint32_t dst = vdst0 + (uint32_t)(srow[i] * VSTRIDE + sc4 * 4) * 4;
        CP_ASYNC16(dst, Vg + (size_t)srow[i] * (H_DIM * 64) + sc4 * 4);
    }
    CP_COMMIT();
    float4 kr[4];
    #pragma unroll
    for (int i = 0; i < 4; i++)
        kr[i] = *(const float4*)(Kg + (size_t)srow[i] * (H_DIM * 64) + sc4 * 4);

    for (int t = 0; t < NTILES; ++t) {
        const int buf = t & 1;
        const int s0 = t * BC;

        // stage K(t): convert kr -> bf16 hi/mid into buffer buf
        {
            uint32_t* kdst = smu + OFF_K + buf * KBUF;
            #pragma unroll
            for (int i = 0; i < 4; i++) {
                float4 x = kr[i];
                uint32_t h0 = pack_bf16(x.x, x.y);
                uint32_t h1 = pack_bf16(x.z, x.w);
                uint32_t m0p = pack_bf16(x.x - bf16lo_f(h0), x.y - bf16hi_f(h0));
                uint32_t m1p = pack_bf16(x.z - bf16lo_f(h1), x.w - bf16hi_f(h1));
                *(uint2*)(kdst + srow[i] * KS2 + 2 * sc4) = make_uint2(h0, h1);
                *(uint2*)(kdst + 1152 + srow[i] * KS2 + 2 * sc4) = make_uint2(m0p, m1p);
            }
        }

        CP_WAIT0();
        __syncthreads();

        // issue next tile's loads (overlap with compute below)
        if (t + 1 < NTILES) {
            const int s1 = s0 + BC;
            uint32_t vdst = vdst0 + (uint32_t)((1 - buf) * VBUF) * 4;
            #pragma unroll
            for (int i = 0; i < 4; i++) {
                uint32_t dst = vdst + (uint32_t)(srow[i] * VSTRIDE + sc4 * 4) * 4;
                CP_ASYNC16(dst, Vg + (size_t)(s1 + srow[i]) * (H_DIM * 64) + sc4 * 4);
            }
            CP_COMMIT();
            #pragma unroll
            for (int i = 0; i < 4; i++)
                kr[i] = *(const float4*)(Kg + (size_t)(s1 + srow[i]) * (H_DIM * 64) + sc4 * 4);
        }

        const uint32_t* kbh = kbh0 + buf * KBUF;
        const uint32_t* kbm = kbh + 1152;
        const uint32_t* vbp = vbp0 + buf * VBUF;

        // ---- chunk-interleaved: for each 8-col chunk nt:
        //      MMA1(nt) -> softmax(nt) -> MMA2(kt=nt). Unrolled for cross-chunk ILP.
        #pragma unroll
        for (int nt = 0; nt < 4; nt++) {
            // mask LDGs first (latency hides under MMAs)
            float2 ma0 = *(const float2*)(Mr0 + s0 + nt * 8);
            float2 ma1 = *(const float2*)(Mr1 + s0 + nt * 8);
            float2 ma2 = *(const float2*)(Mr2 + s0 + nt * 8);
            float2 ma3 = *(const float2*)(Mr3 + s0 + nt * 8);

            // MMA1 chunk: S(:, nt*8..nt*8+7) both row-groups
            float s0f[4] = {0.f, 0.f, 0.f, 0.f};
            float s1f[4] = {0.f, 0.f, 0.f, 0.f};
            #pragma unroll
            for (int c = 0; c < 4; c++) {
                int off = nt * (8 * KS2) + c * 8;
                uint32_t bh0 = kbh[off], bh1 = kbh[off + 4];
                uint32_t bm0 = kbm[off], bm1 = kbm[off + 4];
                mma_bf16(s0f, qh0 + c * 4, bh0, bh1);
                mma_bf16(s1f, qh1 + c * 4, bh0, bh1);
                mma_bf16(s0f, qm0 + c * 4, bh0, bh1);
                mma_bf16(s1f, qm1 + c * 4, bh0, bh1);
                mma_bf16(s0f, qh0 + c * 4, bm0, bm1);
                mma_bf16(s1f, qh1 + c * 4, bm0, bm1);
            }

            // softmax chunk -> P store
            int mc = (nt * 8 + tg * 2) ^ pxor;
            {
                float p0 = __expf(s0f[0] + TEMP * ma0.x);
                float p1 = __expf(s0f[1] + TEMP * ma0.y);
                float p2 = __expf(s0f[2] + TEMP * ma1.x);
                float p3 = __expf(s0f[3] + TEMP * ma1.y);
                uint32_t q0 = rna_tf32(p0), q1 = rna_tf32(p1);
                uint32_t q2 = rna_tf32(p2), q3 = rna_tf32(p3);
                rs[0] += __uint_as_float(q0) + __uint_as_float(q1);
                rs[1] += __uint_as_float(q2) + __uint_as_float(q3);
                *(uint2*)(prow00 + mc) = make_uint2(q0, q1);
                *(uint2*)(prow01 + mc) = make_uint2(q2, q3);
            }
            {
                float p0 = __expf(s1f[0] + TEMP * ma2.x);
                float p1 = __expf(s1f[1] + TEMP * ma2.y);
                float p2 = __expf(s1f[2] + TEMP * ma3.x);
                float p3 = __expf(s1f[3] + TEMP * ma3.y);
                uint32_t q0 = rna_tf32(p0), q1 = rna_tf32(p1);
                uint32_t q2 = rna_tf32(p2), q3 = rna_tf32(p3);
                rs[2] += __uint_as_float(q0) + __uint_as_float(q1);
                rs[3] += __uint_as_float(q2) + __uint_as_float(q3);
                *(uint2*)(prow10 + mc) = make_uint2(q0, q1);
                *(uint2*)(prow11 + mc) = make_uint2(q2, q3);
            }
            __syncwarp();

            // MMA2 chunk: O += P(:, nt*8..) * V(nt*8.., :)
            int c0 = (nt * 8 + tg) ^ pxor;
            int c1 = (nt * 8 + tg + 4) ^ pxor;
            uint32_t a0[4], a1[4];
            a0[0] = prow00[c0]; a0[1] = prow01[c0];
            a0[2] = prow00[c1]; a0[3] = prow01[c1];
            a1[0] = prow10[c0]; a1[1] = prow11[c0];
            a1[2] = prow10[c1]; a1[3] = prow11[c1];
            #pragma unroll
            for (int nv = 0; nv < 8; nv++) {
                int vo = nt * (8 * VSTRIDE) + nv * 8;
                uint32_t b0 = vbp[vo];
                uint32_t b1 = vbp[vo + 4 * VSTRIDE];
                mma_tf32(oacc0 + nv * 4, a0, b0, b1);
                mma_tf32(oacc1 + nv * 4, a1, b0, b1);
            }
        }
    }

    // ---- epilogue (1+1.7e-4 compensates tf32-truncation bias on V) ----
    #pragma unroll
    for (int i = 0; i < 4; i++) {
        rs[i] += __shfl_xor_sync(0xFFFFFFFFu, rs[i], 1);
        rs[i] += __shfl_xor_sync(0xFFFFFFFFu, rs[i], 2);
    }
    const int qrow0 = qbase + w * 32 + g;
    #pragma unroll
    for (int rg = 0; rg < 2; rg++) {
        const float* oacc = rg ? oacc1 : oacc0;
        const float inv0 = 1.00017f / rs[rg * 2 + 0];
        const float inv1 = 1.00017f / rs[rg * 2 + 1];
        float* Og0 = O + (((size_t)n * L_DIM + qrow0 + rg * 16) * H_DIM + h) * 64;
        float* Og1 = Og0 + (size_t)8 * H_DIM * 64;
        #pragma unroll
        for (int nt = 0; nt < 8; nt++) {
            int c = nt * 8 + tg * 2;
            float2 v0, v1;
            v0.x = oacc[nt * 4 + 0] * inv0;
            v0.y = oacc[nt * 4 + 1] * inv0;
            v1.x = oacc[nt * 4 + 2] * inv1;
            v1.y = oacc[nt * 4 + 3] * inv1;
            *(float2*)(Og0 + c) = v0;
            *(float2*)(Og1 + c) = v1;
        }
    }
}

extern "C" void kernel_launch(void* const* d_in, const int* in_sizes, int n_in,
                              void* d_out, int out_size)
{
    (void)in_sizes; (void)n_in; (void)out_size;
    const float* q = (const float*)d_in[0];
    const float* k = (const float*)d_in[1];
    const float* v = (const float*)d_in[2];
    const float* m = (const float*)d_in[3];
    float* o = (float*)d_out;

    cudaFuncSetAttribute(attn_mma5_kernel, cudaFuncAttributeMaxDynamicSharedMemorySize, SMEM_BYTES);

    dim3 grid(N_DIM * H_DIM * (L_DIM / BR));   // 512
    dim3 block(128);
    attn_mma5_kernel<<<grid, block, SMEM_BYTES>>>(q, k, v, m, o);
}

// round 8
// speedup vs baseline: 1.1460x; 1.1460x over previous
#include <cuda_runtime.h>
#include <cuda_fp16.h>
#include <cstdint>
#include <cstddef>

// Flash attention, warp-mma mixed precision, pipelined, m32-per-warp (R6 base):
//   QK^T: fp16 2-term split (m16n8k16): (qh+qm)*kh; K single fp16 (err 2^-11)
//   PV:   tf32 m16n8k8 on raw f32 V (HW truncation) + bias compensation
//   B-fragments (K, V) loaded once per warp, reused by both row-groups.
//   V via cp.async double-buffered; K LDG-prefetch + convert, double-buffered.
//   One __syncthreads per KV tile. Monolithic phases (R7 interleave regressed).

#define N_DIM 2
#define L_DIM 2048
#define S_DIM 2048
#define H_DIM 16
#define BR 128
#define BC 32
#define NTILES (S_DIM / BC)
#define TEMP 0.125f

// smem word offsets
#define KS2 36                        // kh row stride (fp16x2 words)
#define VSTRIDE 72
#define PSTRIDE 40
#define QSTRIDE 68
#define KBUF 1152                     // per K buffer: kh only (32*36)
#define OFF_K 0                       // 2 buffers -> 2304
#define OFF_V 2304                    // 2 buffers x 2304
#define VBUF 2304
#define OFF_P 6912                    // 4 warps * 32 rows * 40 = 5120
#define SMEM_WORDS 12032              // 48128 B (dynamic)
#define SMEM_BYTES (SMEM_WORDS * 4)

__device__ __forceinline__ uint32_t pack_f16(float lo, float hi) {
    uint32_t r; asm("cvt.rn.f16x2.f32 %0, %1, %2;" : "=r"(r) : "f"(hi), "f"(lo)); return r;
}
__device__ __forceinline__ float2 unpack_f16(uint32_t u) {
    __half2 h = *reinterpret_cast<__half2*>(&u);
    return __half22float2(h);
}
__device__ __forceinline__ uint32_t rna_tf32(float x) {
    uint32_t r; asm("cvt.rna.tf32.f32 %0, %1;" : "=r"(r) : "f"(x)); return r;
}

__device__ __forceinline__ void mma_f16(float* d, const uint32_t* a, uint32_t b0, uint32_t b1) {
    asm volatile(
        "mma.sync.aligned.m16n8k16.row.col.f32.f16.f16.f32 "
        "{%0,%1,%2,%3}, {%4,%5,%6,%7}, {%8,%9}, {%0,%1,%2,%3};"
        : "+f"(d[0]), "+f"(d[1]), "+f"(d[2]), "+f"(d[3])
        : "r"(a[0]), "r"(a[1]), "r"(a[2]), "r"(a[3]), "r"(b0), "r"(b1));
}
__device__ __forceinline__ void mma_tf32(float* d, const uint32_t* a, uint32_t b0, uint32_t b1) {
    asm volatile(
        "mma.sync.aligned.m16n8k8.row.col.f32.tf32.tf32.f32 "
        "{%0,%1,%2,%3}, {%4,%5,%6,%7}, {%8,%9}, {%0,%1,%2,%3};"
        : "+f"(d[0]), "+f"(d[1]), "+f"(d[2]), "+f"(d[3])
        : "r"(a[0]), "r"(a[1]), "r"(a[2]), "r"(a[3]), "r"(b0), "r"(b1));
}

#define CP_ASYNC16(dst, src) \
    asm volatile("cp.async.cg.shared.global [%0], [%1], 16;" :: "r"(dst), "l"(src))
#define CP_COMMIT() asm volatile("cp.async.commit_group;" ::: "memory")
#define CP_WAIT0()  asm volatile("cp.async.wait_group 0;" ::: "memory")

__global__ __launch_bounds__(128, 2) void attn_mma6_kernel(
    const float* __restrict__ Q,
    const float* __restrict__ K,
    const float* __restrict__ V,
    const float* __restrict__ M,
    float* __restrict__ O)
{
    extern __shared__ float sm[];
    uint32_t* smu = (uint32_t*)sm;

    const int tid  = threadIdx.x;
    const int w    = tid >> 5;
    const int lane = tid & 31;
    const int g    = lane >> 2;
    const int tg   = lane & 3;
    const int pxor = (g & 4);

    const int qt = blockIdx.x % (L_DIM / BR);
    const int nh = blockIdx.x / (L_DIM / BR);
    const int h  = nh % H_DIM;
    const int n  = nh / H_DIM;
    const int qbase = qt * BR;

    const float* Qg = Q + (((size_t)n * L_DIM + qbase) * H_DIM + h) * 64;
    const float* Kg = K + ((size_t)n * S_DIM * H_DIM + h) * 64;
    const float* Vg = V + ((size_t)n * S_DIM * H_DIM + h) * 64;

    const int srow[4] = { tid >> 4, (128 + tid) >> 4, (256 + tid) >> 4, (384 + tid) >> 4 };
    const int sc4 = tid & 15;

    // ---- Prologue: Q (128x64) -> smem scratch -> fp16 hi/mid A frags ----
    #pragma unroll
    for (int i = 0; i < 16; i++) {
        int idx = i * 128 + tid;
        int row = idx >> 4, c4 = idx & 15;
        float4 v = *(const float4*)(Qg + (size_t)row * (H_DIM * 64) + c4 * 4);
        *(float4*)(sm + row * QSTRIDE + c4 * 4) = v;
    }
    __syncthreads();

    uint32_t qh0[16], qm0[16], qh1[16], qm1[16];
    #pragma unroll
    for (int rg = 0; rg < 2; rg++) {
        uint32_t* qh = rg ? qh1 : qh0;
        uint32_t* qm = rg ? qm1 : qm0;
        const int r0 = w * 32 + rg * 16 + g;
        #pragma unroll
        for (int c = 0; c < 4; c++) {          // k16 chunk over E
            #pragma unroll
            for (int j = 0; j < 4; j++) {      // a0..a3
                int row = r0 + ((j & 1) ? 8 : 0);
                int col = c * 16 + 2 * tg + ((j & 2) ? 8 : 0);
                float2 v = *(const float2*)(sm + row * QSTRIDE + col);
                float x0 = v.x * TEMP, x1 = v.y * TEMP;
                uint32_t hp = pack_f16(x0, x1);
                float2 hf = unpack_f16(hp);
                qh[c * 4 + j] = hp;
                qm[c * 4 + j] = pack_f16(x0 - hf.x, x1 - hf.y);
            }
        }
    }
    __syncthreads();   // scratch reads done before staging overwrites

    float oacc0[32], oacc1[32];
    #pragma unroll
    for (int i = 0; i < 32; i++) { oacc0[i] = 0.0f; oacc1[i] = 0.0f; }
    float rs[4] = {0.0f, 0.0f, 0.0f, 0.0f};

    const uint32_t* kbh0 = smu + OFF_K + g * KS2 + tg;
    const uint32_t* vbp0 = smu + OFF_V + tg * VSTRIDE + g;
    uint32_t* prow00 = smu + OFF_P + (w * 32 + g) * PSTRIDE;
    uint32_t* prow01 = prow00 + 8 * PSTRIDE;
    uint32_t* prow10 = prow00 + 16 * PSTRIDE;
    uint32_t* prow11 = prow00 + 24 * PSTRIDE;

    const float* Mr0 = M + (size_t)(qbase + w * 32 + g) * S_DIM + tg * 2;
    const float* Mr1 = Mr0 + (size_t)8 * S_DIM;
    const float* Mr2 = Mr0 + (size_t)16 * S_DIM;
    const float* Mr3 = Mr0 + (size_t)24 * S_DIM;

    const uint32_t vdst0 = (uint32_t)__cvta_generic_to_shared(smu + OFF_V);

    // issue cp.async V(0), LDG K(0)
    #pragma unroll
    for (int i = 0; i < 4; i++) {
        uint32_t dst = vdst0 + (uint32_t)(srow[i] * VSTRIDE + sc4 * 4) * 4;
        CP_ASYNC16(dst, Vg + (size_t)srow[i] * (H_DIM * 64) + sc4 * 4);
    }
    CP_COMMIT();
    float4 kr[4];
    #pragma unroll
    for (int i = 0; i < 4; i++)
        kr[i] = *(const float4*)(Kg + (size_t)srow[i] * (H_DIM * 64) + sc4 * 4);

    for (int t = 0; t < NTILES; ++t) {
        const int buf = t & 1;
        const int s0 = t * BC;

        // stage K(t): convert kr -> fp16 (single term) into buffer buf
        {
            uint32_t* kdst = smu + OFF_K + buf * KBUF;
            #pragma unroll
            for (int i = 0; i < 4; i++) {
                float4 x = kr[i];
                uint32_t h0 = pack_f16(x.x, x.y);
                uint32_t h1 = pack_f16(x.z, x.w);
                *(uint2*)(kdst + srow[i] * KS2 + 2 * sc4) = make_uint2(h0, h1);
            }
        }

        CP_WAIT0();        // V(t) arrived
        __syncthreads();   // K(t) STS + V(t) visible; compute(t-1) done everywhere

        // issue next tile's loads (overlapped with compute below)
        if (t + 1 < NTILES) {
            const int s1 = s0 + BC;
            uint32_t vdst = vdst0 + (uint32_t)((1 - buf) * VBUF) * 4;
            #pragma unroll
            for (int i = 0; i < 4; i++) {
                uint32_t dst = vdst + (uint32_t)(srow[i] * VSTRIDE + sc4 * 4) * 4;
                CP_ASYNC16(dst, Vg + (size_t)(s1 + srow[i]) * (H_DIM * 64) + sc4 * 4);
            }
            CP_COMMIT();
            #pragma unroll
            for (int i = 0; i < 4; i++)
                kr[i] = *(const float4*)(Kg + (size_t)(s1 + srow[i]) * (H_DIM * 64) + sc4 * 4);
        }

        // ---- MMA1: S = (qh + qm) * kh, fp16 m16n8k16, B shared by row-groups ----
        const uint32_t* kbh = kbh0 + buf * KBUF;
        float s0f[16], s1f[16];
        #pragma unroll
        for (int i = 0; i < 16; i++) { s0f[i] = 0.0f; s1f[i] = 0.0f; }
        #pragma unroll
        for (int c = 0; c < 4; c++) {
            #pragma unroll
            for (int nt = 0; nt < 4; nt++) {
                int off = nt * (8 * KS2) + c * 8;
                uint32_t bh0 = kbh[off], bh1 = kbh[off + 4];
                mma_f16(s0f + nt * 4, qh0 + c * 4, bh0, bh1);
                mma_f16(s1f + nt * 4, qh1 + c * 4, bh0, bh1);
                mma_f16(s0f + nt * 4, qm0 + c * 4, bh0, bh1);
                mma_f16(s1f + nt * 4, qm1 + c * 4, bh0, bh1);
            }
        }

        // ---- softmax -> P (tf32-rounded; rowsum over rounded p) ----
        #pragma unroll
        for (int nt = 0; nt < 4; nt++) {
            int mc = (nt * 8 + tg * 2) ^ pxor;
            {
                float2 a = *(const float2*)(Mr0 + s0 + nt * 8);
                float2 b = *(const float2*)(Mr1 + s0 + nt * 8);
                float p0 = __expf(s0f[nt * 4 + 0] + TEMP * a.x);
                float p1 = __expf(s0f[nt * 4 + 1] + TEMP * a.y);
                float p2 = __expf(s0f[nt * 4 + 2] + TEMP * b.x);
                float p3 = __expf(s0f[nt * 4 + 3] + TEMP * b.y);
                uint32_t q0 = rna_tf32(p0), q1 = rna_tf32(p1);
                uint32_t q2 = rna_tf32(p2), q3 = rna_tf32(p3);
                rs[0] += __uint_as_float(q0) + __uint_as_float(q1);
                rs[1] += __uint_as_float(q2) + __uint_as_float(q3);
                *(uint2*)(prow00 + mc) = make_uint2(q0, q1);
                *(uint2*)(prow01 + mc) = make_uint2(q2, q3);
            }
            {
                float2 a = *(const float2*)(Mr2 + s0 + nt * 8);
                float2 b = *(const float2*)(Mr3 + s0 + nt * 8);
                float p0 = __expf(s1f[nt * 4 + 0] + TEMP * a.x);
                float p1 = __expf(s1f[nt * 4 + 1] + TEMP * a.y);
                float p2 = __expf(s1f[nt * 4 + 2] + TEMP * b.x);
                float p3 = __expf(s1f[nt * 4 + 3] + TEMP * b.y);
                uint32_t q0 = rna_tf32(p0), q1 = rna_tf32(p1);
                uint32_t q2 = rna_tf32(p2), q3 = rna_tf32(p3);
                rs[2] += __uint_as_float(q0) + __uint_as_float(q1);
                rs[3] += __uint_as_float(q2) + __uint_as_float(q3);
                *(uint2*)(prow10 + mc) = make_uint2(q0, q1);
                *(uint2*)(prow11 + mc) = make_uint2(q2, q3);
            }
        }
        __syncwarp();

        // ---- MMA2: O += P * V (raw f32 V; tf32 truncation), B shared by row-groups ----
        const uint32_t* vbp = vbp0 + buf * VBUF;
        #pragma unroll
        for (int kt = 0; kt < 4; kt++) {
            int c0 = (kt * 8 + tg) ^ pxor;
            int c1 = (kt * 8 + tg + 4) ^ pxor;
            uint32_t a0[4], a1[4];
            a0[0] = prow00[c0]; a0[1] = prow01[c0];
            a0[2] = prow00[c1]; a0[3] = prow01[c1];
            a1[0] = prow10[c0]; a1[1] = prow11[c0];
            a1[2] = prow10[c1]; a1[3] = prow11[c1];
            #pragma unroll
            for (int nv = 0; nv < 8; nv++) {
                int vo = kt * (8 * VSTRIDE) + nv * 8;
                uint32_t b0 = vbp[vo];
                uint32_t b1 = vbp[vo + 4 * VSTRIDE];
                mma_tf32(oacc0 + nv * 4, a0, b0, b1);
                mma_tf32(oacc1 + nv * 4, a1, b0, b1);
            }
        }
        __syncwarp();
    }

    // ---- epilogue (1+1.7e-4 compensates tf32-truncation bias on V) ----
    #pragma unroll
    for (int i = 0; i < 4; i++) {
        rs[i] += __shfl_xor_sync(0xFFFFFFFFu, rs[i], 1);
        rs[i] += __shfl_xor_sync(0xFFFFFFFFu, rs[i], 2);
    }
    const int qrow0 = qbase + w * 32 + g;
    #pragma unroll
    for (int rg = 0; rg < 2; rg++) {
        const float* oacc = rg ? oacc1 : oacc0;
        const float inv0 = 1.00017f / rs[rg * 2 + 0];
        const float inv1 = 1.00017f / rs[rg * 2 + 1];
        float* Og0 = O + (((size_t)n * L_DIM + qrow0 + rg * 16) * H_DIM + h) * 64;
        float* Og1 = Og0 + (size_t)8 * H_DIM * 64;
        #pragma unroll
        for (int nt = 0; nt < 8; nt++) {
            int c = nt * 8 + tg * 2;
            float2 v0, v1;
            v0.x = oacc[nt * 4 + 0] * inv0;
            v0.y = oacc[nt * 4 + 1] * inv0;
            v1.x = oacc[nt * 4 + 2] * inv1;
            v1.y = oacc[nt * 4 + 3] * inv1;
            *(float2*)(Og0 + c) = v0;
            *(float2*)(Og1 + c) = v1;
        }
    }
}

extern "C" void kernel_launch(void* const* d_in, const int* in_sizes, int n_in,
                              void* d_out, int out_size)
{
    (void)in_sizes; (void)n_in; (void)out_size;
    const float* q = (const float*)d_in[0];
    const float* k = (const float*)d_in[1];
    const float* v = (const float*)d_in[2];
    const float* m = (const float*)d_in[3];
    float* o = (float*)d_out;

    cudaFuncSetAttribute(attn_mma6_kernel, cudaFuncAttributeMaxDynamicSharedMemorySize, SMEM_BYTES);

    dim3 grid(N_DIM * H_DIM * (L_DIM / BR));   // 512
    dim3 block(128);
    attn_mma6_kernel<<<grid, block, SMEM_BYTES>>>(q, k, v, m, o);
}

// round 9
// speedup vs baseline: 1.5056x; 1.3139x over previous
#include <cuda_runtime.h>
#include <cuda_fp16.h>
#include <cstdint>
#include <cstddef>

// Flash attention, all-fp16 operand path, ldmatrix fragments, pipelined, m32/warp:
//   QK^T: fp16 2-term split (m16n8k16): (qh+qm)*kh
//   PV:   fp16 m16n8k16, f32 accum; P fp16-rounded, rowsum over rounded p
//   K/P frags via ldmatrix.x4; V frags via ldmatrix.x4.trans (k-major V).
//   K,V LDG-prefetched one tile ahead, converted to fp16, double-buffered.
//   One __syncthreads per KV tile.

#define N_DIM 2
#define L_DIM 2048
#define S_DIM 2048
#define H_DIM 16
#define BR 128
#define BC 32
#define NTILES (S_DIM / BC)
#define TEMP 0.125f

// smem byte layout
#define KROWB 144              // 64 fp16 = 128 B + 16 pad
#define VROWB 144
#define PROWB 80               // 32 fp16 = 64 B + 16 pad
#define KBUFB 4608             // 32 * 144
#define VBUFB 4608
#define OFF_KB 0               // 2 buffers -> 9216
#define OFF_VB 9216            // 2 buffers -> 9216
#define OFF_PB 18432           // 4 warps * 32 rows * 80 = 10240 -> 28672
#define QSTRIDE 68             // prologue scratch stride (floats)
#define SMEM_BYTES 34816       // max(28672, 128*68*4 = 34816)

__device__ __forceinline__ uint32_t pack_f16(float lo, float hi) {
    uint32_t r; asm("cvt.rn.f16x2.f32 %0, %1, %2;" : "=r"(r) : "f"(hi), "f"(lo)); return r;
}
__device__ __forceinline__ float2 unpack_f16(uint32_t u) {
    __half2 h = *reinterpret_cast<__half2*>(&u);
    return __half22float2(h);
}

__device__ __forceinline__ void mma_f16(float* d, const uint32_t* a, uint32_t b0, uint32_t b1) {
    asm volatile(
        "mma.sync.aligned.m16n8k16.row.col.f32.f16.f16.f32 "
        "{%0,%1,%2,%3}, {%4,%5,%6,%7}, {%8,%9}, {%0,%1,%2,%3};"
        : "+f"(d[0]), "+f"(d[1]), "+f"(d[2]), "+f"(d[3])
        : "r"(a[0]), "r"(a[1]), "r"(a[2]), "r"(a[3]), "r"(b0), "r"(b1));
}

#define LDSM_X4(r0, r1, r2, r3, a) \
    asm volatile("ldmatrix.sync.aligned.m8n8.x4.shared.b16 {%0,%1,%2,%3}, [%4];" \
        : "=r"(r0), "=r"(r1), "=r"(r2), "=r"(r3) : "r"(a))
#define LDSM_X4_T(r0, r1, r2, r3, a) \
    asm volatile("ldmatrix.sync.aligned.m8n8.x4.trans.shared.b16 {%0,%1,%2,%3}, [%4];" \
        : "=r"(r0), "=r"(r1), "=r"(r2), "=r"(r3) : "r"(a))

__global__ __launch_bounds__(128, 2) void attn_mma7_kernel(
    const float* __restrict__ Q,
    const float* __restrict__ K,
    const float* __restrict__ V,
    const float* __restrict__ M,
    float* __restrict__ O)
{
    __shared__ __align__(128) char smb[SMEM_BYTES];
    float* smf = (float*)smb;
    const uint32_t smu = (uint32_t)__cvta_generic_to_shared(smb);

    const int tid  = threadIdx.x;
    const int w    = tid >> 5;
    const int lane = tid & 31;
    const int g    = lane >> 2;
    const int tg   = lane & 3;
    const int mm   = lane >> 3;    // ldmatrix matrix index 0-3
    const int rr   = lane & 7;     // ldmatrix row-in-matrix

    const int qt = blockIdx.x % (L_DIM / BR);
    const int nh = blockIdx.x / (L_DIM / BR);
    const int h  = nh % H_DIM;
    const int n  = nh / H_DIM;
    const int qbase = qt * BR;

    const float* Qg = Q + (((size_t)n * L_DIM + qbase) * H_DIM + h) * 64;
    const float* Kg = K + ((size_t)n * S_DIM * H_DIM + h) * 64;
    const float* Vg = V + ((size_t)n * S_DIM * H_DIM + h) * 64;

    const int srow[4] = { tid >> 4, (128 + tid) >> 4, (256 + tid) >> 4, (384 + tid) >> 4 };
    const int sc4 = tid & 15;

    // ---- Prologue: Q (128x64) -> smem scratch -> fp16 hi/mid A frags ----
    #pragma unroll
    for (int i = 0; i < 16; i++) {
        int idx = i * 128 + tid;
        int row = idx >> 4, c4 = idx & 15;
        float4 v = *(const float4*)(Qg + (size_t)row * (H_DIM * 64) + c4 * 4);
        *(float4*)(smf + row * QSTRIDE + c4 * 4) = v;
    }
    __syncthreads();

    uint32_t qh0[16], qm0[16], qh1[16], qm1[16];
    #pragma unroll
    for (int rg = 0; rg < 2; rg++) {
        uint32_t* qh = rg ? qh1 : qh0;
        uint32_t* qm = rg ? qm1 : qm0;
        const int r0 = w * 32 + rg * 16 + g;
        #pragma unroll
        for (int c = 0; c < 4; c++) {          // k16 chunk over E
            #pragma unroll
            for (int j = 0; j < 4; j++) {      // a0..a3
                int row = r0 + ((j & 1) ? 8 : 0);
                int col = c * 16 + 2 * tg + ((j & 2) ? 8 : 0);
                float2 v = *(const float2*)(smf + row * QSTRIDE + col);
                float x0 = v.x * TEMP, x1 = v.y * TEMP;
                uint32_t hp = pack_f16(x0, x1);
                float2 hf = unpack_f16(hp);
                qh[c * 4 + j] = hp;
                qm[c * 4 + j] = pack_f16(x0 - hf.x, x1 - hf.y);
            }
        }
    }
    __syncthreads();   // scratch reads done before staging overwrites

    float oacc0[32], oacc1[32];
    #pragma unroll
    for (int i = 0; i < 32; i++) { oacc0[i] = 0.0f; oacc1[i] = 0.0f; }
    float rs[4] = {0.0f, 0.0f, 0.0f, 0.0f};

    // per-lane ldmatrix base addresses (shared-space bytes)
    // K (non-trans): m0=(nt,klo) m1=(nt,khi) m2=(nt+1,klo) m3=(nt+1,khi)
    const uint32_t kadr0 = smu + OFF_KB + (uint32_t)(((mm >> 1) * 8 + rr) * KROWB + (mm & 1) * 16);
    // V (trans):     m0=(nv,klo) m1=(nv,khi) m2=(nv+1,klo) m3=(nv+1,khi)
    const uint32_t vadr0 = smu + OFF_VB + (uint32_t)(((mm & 1) * 8 + rr) * VROWB + (mm >> 1) * 16);
    // P (non-trans): m0=(rows0-7,klo) m1=(rows8-15,klo) m2=(rows0-7,khi) m3=(rows8-15,khi)
    const uint32_t padr0 = smu + OFF_PB + (uint32_t)(w * 2560 + ((mm & 1) * 8 + rr) * PROWB + (mm >> 1) * 16);

    // P store pointers (generic)
    uint32_t* P00 = (uint32_t*)(smb + OFF_PB + w * 2560 + g * PROWB);   // rg0 row g
    uint32_t* P01 = P00 + 8 * (PROWB / 4);                              // rg0 row g+8
    uint32_t* P10 = P00 + 16 * (PROWB / 4);                             // rg1 row g
    uint32_t* P11 = P00 + 24 * (PROWB / 4);                             // rg1 row g+8

    const float* Mr0 = M + (size_t)(qbase + w * 32 + g) * S_DIM + tg * 2;
    const float* Mr1 = Mr0 + (size_t)8 * S_DIM;
    const float* Mr2 = Mr0 + (size_t)16 * S_DIM;
    const float* Mr3 = Mr0 + (size_t)24 * S_DIM;

    // prefetch tile 0 (K and V) into registers
    float4 kr[4], vr[4];
    #pragma unroll
    for (int i = 0; i < 4; i++) {
        kr[i] = *(const float4*)(Kg + (size_t)srow[i] * (H_DIM * 64) + sc4 * 4);
        vr[i] = *(const float4*)(Vg + (size_t)srow[i] * (H_DIM * 64) + sc4 * 4);
    }

    for (int t = 0; t < NTILES; ++t) {
        const int buf = t & 1;
        const int s0 = t * BC;

        // stage K(t), V(t): convert f32 -> fp16x2, store into buffer buf
        {
            char* kdst = smb + OFF_KB + buf * KBUFB;
            char* vdst = smb + OFF_VB + buf * VBUFB;
            #pragma unroll
            for (int i = 0; i < 4; i++) {
                float4 x = kr[i];
                *(uint2*)(kdst + srow[i] * KROWB + sc4 * 8) =
                    make_uint2(pack_f16(x.x, x.y), pack_f16(x.z, x.w));
                float4 y = vr[i];
                *(uint2*)(vdst + srow[i] * VROWB + sc4 * 8) =
                    make_uint2(pack_f16(y.x, y.y), pack_f16(y.z, y.w));
            }
        }
        __syncthreads();   // staging visible; compute(t-1) done everywhere

        // prefetch next tile (overlaps with compute below)
        if (t + 1 < NTILES) {
            const int s1 = s0 + BC;
            #pragma unroll
            for (int i = 0; i < 4; i++) {
                kr[i] = *(const float4*)(Kg + (size_t)(s1 + srow[i]) * (H_DIM * 64) + sc4 * 4);
                vr[i] = *(const float4*)(Vg + (size_t)(s1 + srow[i]) * (H_DIM * 64) + sc4 * 4);
            }
        }

        // ---- MMA1: S = (qh + qm) * kh, B frags via ldmatrix, shared by row-groups ----
        const uint32_t kadr = kadr0 + buf * KBUFB;
        float s0f[16], s1f[16];
        #pragma unroll
        for (int i = 0; i < 16; i++) { s0f[i] = 0.0f; s1f[i] = 0.0f; }
        #pragma unroll
        for (int c = 0; c < 4; c++) {
            uint32_t b00, b01, b10, b11, b20, b21, b30, b31;
            LDSM_X4(b00, b01, b10, b11, kadr + c * 32);          // nt 0,1
            LDSM_X4(b20, b21, b30, b31, kadr + c * 32 + 2304);   // nt 2,3
            mma_f16(s0f + 0,  qh0 + c * 4, b00, b01);
            mma_f16(s0f + 0,  qm0 + c * 4, b00, b01);
            mma_f16(s1f + 0,  qh1 + c * 4, b00, b01);
            mma_f16(s1f + 0,  qm1 + c * 4, b00, b01);
            mma_f16(s0f + 4,  qh0 + c * 4, b10, b11);
            mma_f16(s0f + 4,  qm0 + c * 4, b10, b11);
            mma_f16(s1f + 4,  qh1 + c * 4, b10, b11);
            mma_f16(s1f + 4,  qm1 + c * 4, b10, b11);
            mma_f16(s0f + 8,  qh0 + c * 4, b20, b21);
            mma_f16(s0f + 8,  qm0 + c * 4, b20, b21);
            mma_f16(s1f + 8,  qh1 + c * 4, b20, b21);
            mma_f16(s1f + 8,  qm1 + c * 4, b20, b21);
            mma_f16(s0f + 12, qh0 + c * 4, b30, b31);
            mma_f16(s0f + 12, qm0 + c * 4, b30, b31);
            mma_f16(s1f + 12, qh1 + c * 4, b30, b31);
            mma_f16(s1f + 12, qm1 + c * 4, b30, b31);
        }

        // ---- softmax -> P (fp16-rounded; rowsum over rounded p) ----
        #pragma unroll
        for (int nt = 0; nt < 4; nt++) {
            int mc = nt * 4 + tg;
            {
                float2 a = *(const float2*)(Mr0 + s0 + nt * 8);
                float2 b = *(const float2*)(Mr1 + s0 + nt * 8);
                float p0 = __expf(s0f[nt * 4 + 0] + TEMP * a.x);
                float p1 = __expf(s0f[nt * 4 + 1] + TEMP * a.y);
                float p2 = __expf(s0f[nt * 4 + 2] + TEMP * b.x);
                float p3 = __expf(s0f[nt * 4 + 3] + TEMP * b.y);
                uint32_t u01 = pack_f16(p0, p1);
                uint32_t u23 = pack_f16(p2, p3);
                float2 t01 = unpack_f16(u01);
                float2 t23 = unpack_f16(u23);
                rs[0] += t01.x + t01.y;
                rs[1] += t23.x + t23.y;
                P00[mc] = u01;
                P01[mc] = u23;
            }
            {
                float2 a = *(const float2*)(Mr2 + s0 + nt * 8);
                float2 b = *(const float2*)(Mr3 + s0 + nt * 8);
                float p0 = __expf(s1f[nt * 4 + 0] + TEMP * a.x);
                float p1 = __expf(s1f[nt * 4 + 1] + TEMP * a.y);
                float p2 = __expf(s1f[nt * 4 + 2] + TEMP * b.x);
                float p3 = __expf(s1f[nt * 4 + 3] + TEMP * b.y);
                uint32_t u01 = pack_f16(p0, p1);
                uint32_t u23 = pack_f16(p2, p3);
                float2 t01 = unpack_f16(u01);
                float2 t23 = unpack_f16(u23);
                rs[2] += t01.x + t01.y;
                rs[3] += t23.x + t23.y;
                P10[mc] = u01;
                P11[mc] = u23;
            }
        }
        __syncwarp();

        // ---- MMA2: O += P * V, fp16 m16n8k16; A via ldmatrix, B via ldmatrix.trans ----
        const uint32_t vadr = vadr0 + buf * VBUFB;
        #pragma unroll
        for (int kc = 0; kc < 2; kc++) {
            uint32_t a0[4], a1[4];
            LDSM_X4(a0[0], a0[1], a0[2], a0[3], padr0 + kc * 32);          // rg0
            LDSM_X4(a1[0], a1[1], a1[2], a1[3], padr0 + 1280 + kc * 32);   // rg1
            #pragma unroll
            for (int nvp = 0; nvp < 8; nvp += 2) {
                uint32_t v0, v1, v2, v3;
                LDSM_X4_T(v0, v1, v2, v3, vadr + kc * 2304 + nvp * 16);
                mma_f16(oacc0 + nvp * 4,     a0, v0, v1);
                mma_f16(oacc0 + nvp * 4 + 4, a0, v2, v3);
                mma_f16(oacc1 + nvp * 4,     a1, v0, v1);
                mma_f16(oacc1 + nvp * 4 + 4, a1, v2, v3);
            }
        }
        __syncwarp();
    }

    // ---- epilogue (fp16 rn rounding is unbiased; no compensation) ----
    #pragma unroll
    for (int i = 0; i < 4; i++) {
        rs[i] += __shfl_xor_sync(0xFFFFFFFFu, rs[i], 1);
        rs[i] += __shfl_xor_sync(0xFFFFFFFFu, rs[i], 2);
    }
    const int qrow0 = qbase + w * 32 + g;
    #pragma unroll
    for (int rg = 0; rg < 2; rg++) {
        const float* oacc = rg ? oacc1 : oacc0;
        const float inv0 = 1.0f / rs[rg * 2 + 0];
        const float inv1 = 1.0f / rs[rg * 2 + 1];
        float* Og0 = O + (((size_t)n * L_DIM + qrow0 + rg * 16) * H_DIM + h) * 64;
        float* Og1 = Og0 + (size_t)8 * H_DIM * 64;
        #pragma unroll
        for (int nt = 0; nt < 8; nt++) {
            int c = nt * 8 + tg * 2;
            float2 v0, v1;
            v0.x = oacc[nt * 4 + 0] * inv0;
            v0.y = oacc[nt * 4 + 1] * inv0;
            v1.x = oacc[nt * 4 + 2] * inv1;
            v1.y = oacc[nt * 4 + 3] * inv1;
            *(float2*)(Og0 + c) = v0;
            *(float2*)(Og1 + c) = v1;
        }
    }
}

extern "C" void kernel_launch(void* const* d_in, const int* in_sizes, int n_in,
                              void* d_out, int out_size)
{
    (void)in_sizes; (void)n_in; (void)out_size;
    const float* q = (const float*)d_in[0];
    const float* k = (const float*)d_in[1];
    const float* v = (const float*)d_in[2];
    const float* m = (const float*)d_in[3];
    float* o = (float*)d_out;

    dim3 grid(N_DIM * H_DIM * (L_DIM / BR));   // 512
    dim3 block(128);
    attn_mma7_kernel<<<grid, block>>>(q, k, v, m, o);
}

// round 10
// speedup vs baseline: 1.7054x; 1.1327x over previous
#include <cuda_runtime.h>
#include <cuda_fp16.h>
#include <cstdint>
#include <cstddef>

// Flash attention, all-fp16 operand path, ldmatrix K/V fragments, pipelined,
// m32/warp, P kept entirely in registers (C-frag of MMA1 == A-frag of MMA2
// for fp16 m16n8k16 after fp16x2 packing -- no smem roundtrip).
//   QK^T: fp16 2-term split (m16n8k16): (qh+qm)*kh
//   PV:   fp16 m16n8k16, f32 accum; P fp16-rounded, rowsum over rounded p

#define N_DIM 2
#define L_DIM 2048
#define S_DIM 2048
#define H_DIM 16
#define BR 128
#define BC 32
#define NTILES (S_DIM / BC)
#define TEMP 0.125f

// smem byte layout
#define KROWB 144              // 64 fp16 = 128 B + 16 pad
#define VROWB 144
#define KBUFB 4608             // 32 * 144
#define VBUFB 4608
#define OFF_KB 0               // 2 buffers -> 9216
#define OFF_VB 9216            // 2 buffers -> 9216 (end 18432)
#define QSTRIDE 68             // prologue scratch stride (floats)
#define SMEM_BYTES 34816       // max(18432, 128*68*4 = 34816) -- Q scratch overlay

__device__ __forceinline__ uint32_t pack_f16(float lo, float hi) {
    uint32_t r; asm("cvt.rn.f16x2.f32 %0, %1, %2;" : "=r"(r) : "f"(hi), "f"(lo)); return r;
}
__device__ __forceinline__ float2 unpack_f16(uint32_t u) {
    __half2 h = *reinterpret_cast<__half2*>(&u);
    return __half22float2(h);
}

__device__ __forceinline__ void mma_f16(float* d, const uint32_t* a, uint32_t b0, uint32_t b1) {
    asm volatile(
        "mma.sync.aligned.m16n8k16.row.col.f32.f16.f16.f32 "
        "{%0,%1,%2,%3}, {%4,%5,%6,%7}, {%8,%9}, {%0,%1,%2,%3};"
        : "+f"(d[0]), "+f"(d[1]), "+f"(d[2]), "+f"(d[3])
        : "r"(a[0]), "r"(a[1]), "r"(a[2]), "r"(a[3]), "r"(b0), "r"(b1));
}

#define LDSM_X4(r0, r1, r2, r3, a) \
    asm volatile("ldmatrix.sync.aligned.m8n8.x4.shared.b16 {%0,%1,%2,%3}, [%4];" \
        : "=r"(r0), "=r"(r1), "=r"(r2), "=r"(r3) : "r"(a))
#define LDSM_X4_T(r0, r1, r2, r3, a) \
    asm volatile("ldmatrix.sync.aligned.m8n8.x4.trans.shared.b16 {%0,%1,%2,%3}, [%4];" \
        : "=r"(r0), "=r"(r1), "=r"(r2), "=r"(r3) : "r"(a))

__global__ __launch_bounds__(128, 2) void attn_mma8_kernel(
    const float* __restrict__ Q,
    const float* __restrict__ K,
    const float* __restrict__ V,
    const float* __restrict__ M,
    float* __restrict__ O)
{
    __shared__ __align__(128) char smb[SMEM_BYTES];
    float* smf = (float*)smb;
    const uint32_t smu = (uint32_t)__cvta_generic_to_shared(smb);

    const int tid  = threadIdx.x;
    const int w    = tid >> 5;
    const int lane = tid & 31;
    const int g    = lane >> 2;
    const int tg   = lane & 3;
    const int mm   = lane >> 3;    // ldmatrix matrix index 0-3
    const int rr   = lane & 7;     // ldmatrix row-in-matrix

    const int qt = blockIdx.x % (L_DIM / BR);
    const int nh = blockIdx.x / (L_DIM / BR);
    const int h  = nh % H_DIM;
    const int n  = nh / H_DIM;
    const int qbase = qt * BR;

    const float* Qg = Q + (((size_t)n * L_DIM + qbase) * H_DIM + h) * 64;
    const float* Kg = K + ((size_t)n * S_DIM * H_DIM + h) * 64;
    const float* Vg = V + ((size_t)n * S_DIM * H_DIM + h) * 64;

    const int srow[4] = { tid >> 4, (128 + tid) >> 4, (256 + tid) >> 4, (384 + tid) >> 4 };
    const int sc4 = tid & 15;

    // ---- Prologue: Q (128x64) -> smem scratch -> fp16 hi/mid A frags ----
    #pragma unroll
    for (int i = 0; i < 16; i++) {
        int idx = i * 128 + tid;
        int row = idx >> 4, c4 = idx & 15;
        float4 v = *(const float4*)(Qg + (size_t)row * (H_DIM * 64) + c4 * 4);
        *(float4*)(smf + row * QSTRIDE + c4 * 4) = v;
    }
    __syncthreads();

    uint32_t qh0[16], qm0[16], qh1[16], qm1[16];
    #pragma unroll
    for (int rg = 0; rg < 2; rg++) {
        uint32_t* qh = rg ? qh1 : qh0;
        uint32_t* qm = rg ? qm1 : qm0;
        const int r0 = w * 32 + rg * 16 + g;
        #pragma unroll
        for (int c = 0; c < 4; c++) {
            #pragma unroll
            for (int j = 0; j < 4; j++) {
                int row = r0 + ((j & 1) ? 8 : 0);
                int col = c * 16 + 2 * tg + ((j & 2) ? 8 : 0);
                float2 v = *(const float2*)(smf + row * QSTRIDE + col);
                float x0 = v.x * TEMP, x1 = v.y * TEMP;
                uint32_t hp = pack_f16(x0, x1);
                float2 hf = unpack_f16(hp);
                qh[c * 4 + j] = hp;
                qm[c * 4 + j] = pack_f16(x0 - hf.x, x1 - hf.y);
            }
        }
    }
    __syncthreads();   // scratch reads done before staging overwrites

    float oacc0[32], oacc1[32];
    #pragma unroll
    for (int i = 0; i < 32; i++) { oacc0[i] = 0.0f; oacc1[i] = 0.0f; }
    float rs[4] = {0.0f, 0.0f, 0.0f, 0.0f};

    // per-lane ldmatrix base addresses (shared-space bytes)
    const uint32_t kadr0 = smu + OFF_KB + (uint32_t)(((mm >> 1) * 8 + rr) * KROWB + (mm & 1) * 16);
    const uint32_t vadr0 = smu + OFF_VB + (uint32_t)(((mm & 1) * 8 + rr) * VROWB + (mm >> 1) * 16);

    const float* Mr0 = M + (size_t)(qbase + w * 32 + g) * S_DIM + tg * 2;
    const float* Mr1 = Mr0 + (size_t)8 * S_DIM;
    const float* Mr2 = Mr0 + (size_t)16 * S_DIM;
    const float* Mr3 = Mr0 + (size_t)24 * S_DIM;

    // prefetch tile 0 (K and V) into registers
    float4 kr[4], vr[4];
    #pragma unroll
    for (int i = 0; i < 4; i++) {
        kr[i] = *(const float4*)(Kg + (size_t)srow[i] * (H_DIM * 64) + sc4 * 4);
        vr[i] = *(const float4*)(Vg + (size_t)srow[i] * (H_DIM * 64) + sc4 * 4);
    }

    for (int t = 0; t < NTILES; ++t) {
        const int buf = t & 1;
        const int s0 = t * BC;

        // stage K(t), V(t): convert f32 -> fp16x2, store into buffer buf
        {
            char* kdst = smb + OFF_KB + buf * KBUFB;
            char* vdst = smb + OFF_VB + buf * VBUFB;
            #pragma unroll
            for (int i = 0; i < 4; i++) {
                float4 x = kr[i];
                *(uint2*)(kdst + srow[i] * KROWB + sc4 * 8) =
                    make_uint2(pack_f16(x.x, x.y), pack_f16(x.z, x.w));
                float4 y = vr[i];
                *(uint2*)(vdst + srow[i] * VROWB + sc4 * 8) =
                    make_uint2(pack_f16(y.x, y.y), pack_f16(y.z, y.w));
            }
        }
        __syncthreads();   // staging visible; compute(t-1) done everywhere

        // prefetch next tile (overlaps with compute below)
        if (t + 1 < NTILES) {
            const int s1 = s0 + BC;
            #pragma unroll
            for (int i = 0; i < 4; i++) {
                kr[i] = *(const float4*)(Kg + (size_t)(s1 + srow[i]) * (H_DIM * 64) + sc4 * 4);
                vr[i] = *(const float4*)(Vg + (size_t)(s1 + srow[i]) * (H_DIM * 64) + sc4 * 4);
            }
        }

        // ---- MMA1: S = (qh + qm) * kh, B frags via ldmatrix, shared by row-groups ----
        const uint32_t kadr = kadr0 + buf * KBUFB;
        float s0f[16], s1f[16];
        #pragma unroll
        for (int i = 0; i < 16; i++) { s0f[i] = 0.0f; s1f[i] = 0.0f; }
        #pragma unroll
        for (int c = 0; c < 4; c++) {
            uint32_t b00, b01, b10, b11, b20, b21, b30, b31;
            LDSM_X4(b00, b01, b10, b11, kadr + c * 32);          // nt 0,1
            LDSM_X4(b20, b21, b30, b31, kadr + c * 32 + 2304);   // nt 2,3
            mma_f16(s0f + 0,  qh0 + c * 4, b00, b01);
            mma_f16(s0f + 0,  qm0 + c * 4, b00, b01);
            mma_f16(s1f + 0,  qh1 + c * 4, b00, b01);
            mma_f16(s1f + 0,  qm1 + c * 4, b00, b01);
            mma_f16(s0f + 4,  qh0 + c * 4, b10, b11);
            mma_f16(s0f + 4,  qm0 + c * 4, b10, b11);
            mma_f16(s1f + 4,  qh1 + c * 4, b10, b11);
            mma_f16(s1f + 4,  qm1 + c * 4, b10, b11);
            mma_f16(s0f + 8,  qh0 + c * 4, b20, b21);
            mma_f16(s0f + 8,  qm0 + c * 4, b20, b21);
            mma_f16(s1f + 8,  qh1 + c * 4, b20, b21);
            mma_f16(s1f + 8,  qm1 + c * 4, b20, b21);
            mma_f16(s0f + 12, qh0 + c * 4, b30, b31);
            mma_f16(s0f + 12, qm0 + c * 4, b30, b31);
            mma_f16(s1f + 12, qh1 + c * 4, b30, b31);
            mma_f16(s1f + 12, qm1 + c * 4, b30, b31);
        }

        // ---- softmax -> P fp16x2 A-fragments, held in registers ----
        // u0[nt*2+0] = rows g cols nt*8+2tg..+1 (rg0), u0[nt*2+1] = rows g+8 (rg0)
        uint32_t u0[8], u1[8];
        #pragma unroll
        for (int nt = 0; nt < 4; nt++) {
            {
                float2 a = *(const float2*)(Mr0 + s0 + nt * 8);
                float2 b = *(const float2*)(Mr1 + s0 + nt * 8);
                float p0 = __expf(s0f[nt * 4 + 0] + TEMP * a.x);
                float p1 = __expf(s0f[nt * 4 + 1] + TEMP * a.y);
                float p2 = __expf(s0f[nt * 4 + 2] + TEMP * b.x);
                float p3 = __expf(s0f[nt * 4 + 3] + TEMP * b.y);
                uint32_t u01 = pack_f16(p0, p1);
                uint32_t u23 = pack_f16(p2, p3);
                float2 t01 = unpack_f16(u01);
                float2 t23 = unpack_f16(u23);
                rs[0] += t01.x + t01.y;
                rs[1] += t23.x + t23.y;
                u0[nt * 2 + 0] = u01;
                u0[nt * 2 + 1] = u23;
            }
            {
                float2 a = *(const float2*)(Mr2 + s0 + nt * 8);
                float2 b = *(const float2*)(Mr3 + s0 + nt * 8);
                float p0 = __expf(s1f[nt * 4 + 0] + TEMP * a.x);
                float p1 = __expf(s1f[nt * 4 + 1] + TEMP * a.y);
                float p2 = __expf(s1f[nt * 4 + 2] + TEMP * b.x);
                float p3 = __expf(s1f[nt * 4 + 3] + TEMP * b.y);
                uint32_t u01 = pack_f16(p0, p1);
                uint32_t u23 = pack_f16(p2, p3);
                float2 t01 = unpack_f16(u01);
                float2 t23 = unpack_f16(u23);
                rs[2] += t01.x + t01.y;
                rs[3] += t23.x + t23.y;
                u1[nt * 2 + 0] = u01;
                u1[nt * 2 + 1] = u23;
            }
        }

        // ---- MMA2: O += P * V, fp16 m16n8k16; A direct from registers ----
        // A frag for k-chunk kc: {u[4kc], u[4kc+1], u[4kc+2], u[4kc+3]}
        const uint32_t vadr = vadr0 + buf * VBUFB;
        #pragma unroll
        for (int kc = 0; kc < 2; kc++) {
            const uint32_t* a0 = u0 + 4 * kc;
            const uint32_t* a1 = u1 + 4 * kc;
            #pragma unroll
            for (int nvp = 0; nvp < 8; nvp += 2) {
                uint32_t v0, v1, v2, v3;
                LDSM_X4_T(v0, v1, v2, v3, vadr + kc * 2304 + nvp * 16);
                mma_f16(oacc0 + nvp * 4,     a0, v0, v1);
                mma_f16(oacc0 + nvp * 4 + 4, a0, v2, v3);
                mma_f16(oacc1 + nvp * 4,     a1, v0, v1);
                mma_f16(oacc1 + nvp * 4 + 4, a1, v2, v3);
            }
        }
    }

    // ---- epilogue ----
    #pragma unroll
    for (int i = 0; i < 4; i++) {
        rs[i] += __shfl_xor_sync(0xFFFFFFFFu, rs[i], 1);
        rs[i] += __shfl_xor_sync(0xFFFFFFFFu, rs[i], 2);
    }
    const int qrow0 = qbase + w * 32 + g;
    #pragma unroll
    for (int rg = 0; rg < 2; rg++) {
        const float* oacc = rg ? oacc1 : oacc0;
        const float inv0 = 1.0f / rs[rg * 2 + 0];
        const float inv1 = 1.0f / rs[rg * 2 + 1];
        float* Og0 = O + (((size_t)n * L_DIM + qrow0 + rg * 16) * H_DIM + h) * 64;
        float* Og1 = Og0 + (size_t)8 * H_DIM * 64;
        #pragma unroll
        for (int nt = 0; nt < 8; nt++) {
            int c = nt * 8 + tg * 2;
            float2 v0, v1;
            v0.x = oacc[nt * 4 + 0] * inv0;
            v0.y = oacc[nt * 4 + 1] * inv0;
            v1.x = oacc[nt * 4 + 2] * inv1;
            v1.y = oacc[nt * 4 + 3] * inv1;
            *(float2*)(Og0 + c) = v0;
            *(float2*)(Og1 + c) = v1;
        }
    }
}

extern "C" void kernel_launch(void* const* d_in, const int* in_sizes, int n_in,
                              void* d_out, int out_size)
{
    (void)in_sizes; (void)n_in; (void)out_size;
    const float* q = (const float*)d_in[0];
    const float* k = (const float*)d_in[1];
    const float* v = (const float*)d_in[2];
    const float* m = (const float*)d_in[3];
    float* o = (float*)d_out;

    dim3 grid(N_DIM * H_DIM * (L_DIM / BR));   // 512
    dim3 block(128);
    attn_mma8_kernel<<<grid, block>>>(q, k, v, m, o);
}